// round 16
// baseline (speedup 1.0000x reference)
#include <cuda_runtime.h>
#include <mma.h>
#include <cuda_bf16.h>
#include <cstdint>

using namespace nvcuda;

#define Bdim 8
#define Hdim 16
#define Sdim 4096
#define Ddim 64
#define Kdim 256
#define BH (Bdim * Hdim)

typedef __nv_bfloat16 bf16;

// ---------------------------------------------------------------------------
// Scratch (no allocation; __device__ globals)
// ---------------------------------------------------------------------------
__device__ bf16 g_pA_hi[(size_t)2 * Sdim * Kdim];      // [which][n][kk]
__device__ bf16 g_pA_lo[(size_t)2 * Sdim * Kdim];
__device__ bf16 g_kpT_hi[(size_t)BH * Ddim * Kdim];    // [bh][d][kk]
__device__ bf16 g_kpT_lo[(size_t)BH * Ddim * Kdim];
__device__ bf16 g_vp_hi[(size_t)BH * Kdim * Ddim];     // [bh][kk][d]
__device__ bf16 g_vp_lo[(size_t)BH * Kdim * Ddim];
__device__ float g_probs_fb[(size_t)BH * Sdim * Kdim]; // fallback if probs==null

// ---------------------------------------------------------------------------
// helpers
// ---------------------------------------------------------------------------
__device__ __forceinline__ uint32_t smem_u32(const void* p) {
    uint32_t a;
    asm("{ .reg .u64 t; cvta.to.shared.u64 t, %1; cvt.u32.u64 %0, t; }"
        : "=r"(a) : "l"(p));
    return a;
}
__device__ __forceinline__ void cpa16(uint32_t dst, const void* src) {
    asm volatile("cp.async.cg.shared.global [%0], [%1], 16;" :: "r"(dst), "l"(src));
}
#define CPA_COMMIT() asm volatile("cp.async.commit_group;" ::: "memory")
#define CPA_WAIT0()  asm volatile("cp.async.wait_group 0;" ::: "memory")

// split float -> bf16 hi + bf16 lo (lo = rn(x - hi))
__device__ __forceinline__ void splitbf(float x, bf16& h, bf16& l) {
    h = __float2bfloat16(x);
    l = __float2bfloat16(x - __bfloat162float(h));
}
__device__ __forceinline__ void split4(float4 v, uint2& ho, uint2& lo) {
    bf16 h0, h1, h2, h3, l0, l1, l2, l3;
    splitbf(v.x, h0, l0); splitbf(v.y, h1, l1);
    splitbf(v.z, h2, l2); splitbf(v.w, h3, l3);
    __nv_bfloat162 hp0(h0, h1), hp1(h2, h3), lp0(l0, l1), lp1(l2, l3);
    ho.x = *(uint32_t*)&hp0; ho.y = *(uint32_t*)&hp1;
    lo.x = *(uint32_t*)&lp0; lo.y = *(uint32_t*)&lp1;
}

// ---------------------------------------------------------------------------
// Pre-pass: split proj_k / proj_v (tiny: 2 x 4 MB)
// ---------------------------------------------------------------------------
__global__ __launch_bounds__(256) void split_plain(
    const float* __restrict__ src, bf16* __restrict__ hi, bf16* __restrict__ lo,
    size_t n4)
{
    for (size_t i = (size_t)blockIdx.x * 256 + threadIdx.x; i < n4;
         i += (size_t)gridDim.x * 256) {
        uint2 h, l;
        split4(((const float4*)src)[i], h, l);
        ((uint2*)hi)[i] = h;
        ((uint2*)lo)[i] = l;
    }
}

// ---------------------------------------------------------------------------
// Stage A: per (bh, which): C[kk=256, d=64] = sum_n proj[n,kk] * (kv[n,d]*m[n])
// 3x-bf16 WMMA. A pre-split via cp.async double-buffer; B via fused
// LDG -> mask+split -> STS double-buffer. 256 thr / 8 warps; 64x32 warp tile.
// ---------------------------------------------------------------------------
#define PA_LDE 264
#define PB_LDE 72
#define SA_B (32 * PA_LDE * 2)
#define SB_B (32 * PB_LDE * 2)
#define OFF_AH 0
#define OFF_AL (2 * SA_B)
#define OFF_BH (4 * SA_B)
#define OFF_BL (4 * SA_B + 2 * SB_B)
#define PROJ_SMEM (4 * SA_B + 4 * SB_B)    // 86016
#define NCH (Sdim / 32)

__global__ __launch_bounds__(256) void proj_gemm(
    const float* __restrict__ kin, const float* __restrict__ vin,
    const float* __restrict__ mask)
{
    extern __shared__ char smraw[];
    const uint32_t sb = smem_u32(smraw);
    const int bh = blockIdx.x, which = blockIdx.y, b = bh >> 4;
    const int t = threadIdx.x, wid = t >> 5;
    const int m0 = (wid & 3) * 64;
    const int n0c = (wid >> 2) * 32;

    const char* Ah = (const char*)(g_pA_hi + (size_t)which * Sdim * Kdim);
    const char* Al = (const char*)(g_pA_lo + (size_t)which * Sdim * Kdim);
    const float* Bg = (which ? vin : kin) + (size_t)bh * Sdim * Ddim;
    const float* mk = mask + (size_t)b * Sdim;

    wmma::fragment<wmma::accumulator, 16, 16, 16, float> acc[4][2];
#pragma unroll
    for (int mi = 0; mi < 4; mi++)
#pragma unroll
        for (int ni = 0; ni < 2; ni++) wmma::fill_fragment(acc[mi][ni], 0.0f);

    float4 br[2];
    float brm[2];

    auto issueA = [&](int ch, int buf) {
        const size_t aoff = (size_t)ch * 32 * 512;
#pragma unroll
        for (int l = 0; l < 4; l++) {
            int c = t + l * 256;
            int row = c >> 5, off = c & 31;
            cpa16(sb + OFF_AH + buf * SA_B + row * 528 + off * 16,
                  Ah + aoff + row * 512 + off * 16);
            cpa16(sb + OFF_AL + buf * SA_B + row * 528 + off * 16,
                  Al + aoff + row * 512 + off * 16);
        }
    };
    auto ldgB = [&](int ch) {
#pragma unroll
        for (int l = 0; l < 2; l++) {
            int idx = t + l * 256;
            int row = idx >> 4, c4 = idx & 15;
            br[l]  = *(const float4*)&Bg[(size_t)(ch * 32 + row) * Ddim + c4 * 4];
            brm[l] = mk[ch * 32 + row];
        }
    };
    auto stsB = [&](int buf) {
        bf16* BHp = (bf16*)(smraw + OFF_BH + buf * SB_B);
        bf16* BLp = (bf16*)(smraw + OFF_BL + buf * SB_B);
#pragma unroll
        for (int l = 0; l < 2; l++) {
            int idx = t + l * 256;
            int row = idx >> 4, c4 = idx & 15;
            float4 v = br[l]; float m = brm[l];
            v.x *= m; v.y *= m; v.z *= m; v.w *= m;
            uint2 h, lo;
            split4(v, h, lo);
            *(uint2*)&BHp[row * PB_LDE + c4 * 4] = h;
            *(uint2*)&BLp[row * PB_LDE + c4 * 4] = lo;
        }
    };
    auto do_mma = [&](int buf) {
        const bf16* AH = (const bf16*)(smraw + OFF_AH + buf * SA_B);
        const bf16* AL = (const bf16*)(smraw + OFF_AL + buf * SA_B);
        const bf16* BHp = (const bf16*)(smraw + OFF_BH + buf * SB_B);
        const bf16* BLp = (const bf16*)(smraw + OFF_BL + buf * SB_B);
#pragma unroll
        for (int ks = 0; ks < 2; ks++) {
            wmma::fragment<wmma::matrix_b, 16, 16, 16, bf16, wmma::row_major> bh2[2], bl2[2];
#pragma unroll
            for (int ni = 0; ni < 2; ni++) {
                wmma::load_matrix_sync(bh2[ni], BHp + (ks * 16) * PB_LDE + n0c + ni * 16, PB_LDE);
                wmma::load_matrix_sync(bl2[ni], BLp + (ks * 16) * PB_LDE + n0c + ni * 16, PB_LDE);
            }
#pragma unroll
            for (int mi = 0; mi < 4; mi++) {
                wmma::fragment<wmma::matrix_a, 16, 16, 16, bf16, wmma::col_major> ah2, al2;
                wmma::load_matrix_sync(ah2, AH + (ks * 16) * PA_LDE + m0 + mi * 16, PA_LDE);
                wmma::load_matrix_sync(al2, AL + (ks * 16) * PA_LDE + m0 + mi * 16, PA_LDE);
#pragma unroll
                for (int ni = 0; ni < 2; ni++) {
                    wmma::mma_sync(acc[mi][ni], ah2, bl2[ni], acc[mi][ni]);
                    wmma::mma_sync(acc[mi][ni], al2, bh2[ni], acc[mi][ni]);
                    wmma::mma_sync(acc[mi][ni], ah2, bh2[ni], acc[mi][ni]);
                }
            }
        }
    };

    ldgB(0);
    issueA(0, 0); CPA_COMMIT();
    CPA_WAIT0();
    stsB(0);
    ldgB(1);
    __syncthreads();

    for (int i = 0; i < NCH; i++) {
        const int cur = i & 1, nxt = cur ^ 1;
        if (i + 1 < NCH) {
            issueA(i + 1, nxt);
            CPA_COMMIT();
            stsB(nxt);
        }
        if (i + 2 < NCH) ldgB(i + 2);
        do_mma(cur);
        if (i + 1 < NCH) CPA_WAIT0();
        __syncthreads();
    }

    float* stage = (float*)smraw;
#pragma unroll
    for (int mi = 0; mi < 4; mi++)
#pragma unroll
        for (int ni = 0; ni < 2; ni++)
            wmma::store_matrix_sync(stage + (size_t)(m0 + mi * 16) * 68 + n0c + ni * 16,
                                    acc[mi][ni], 68, wmma::mem_row_major);
    __syncthreads();

    if (which == 0) {
        bf16* dh = g_kpT_hi + (size_t)bh * Ddim * Kdim;
        bf16* dl = g_kpT_lo + (size_t)bh * Ddim * Kdim;
#pragma unroll
        for (int l = 0; l < 16; l++) {
            int v4i = t + l * 256;
            int d = v4i >> 6, kq = v4i & 63;
            float4 v;
            v.x = stage[(size_t)(kq * 4 + 0) * 68 + d];
            v.y = stage[(size_t)(kq * 4 + 1) * 68 + d];
            v.z = stage[(size_t)(kq * 4 + 2) * 68 + d];
            v.w = stage[(size_t)(kq * 4 + 3) * 68 + d];
            uint2 h, lo2;
            split4(v, h, lo2);
            *(uint2*)&dh[(size_t)d * Kdim + kq * 4] = h;
            *(uint2*)&dl[(size_t)d * Kdim + kq * 4] = lo2;
        }
    } else {
        bf16* dh = g_vp_hi + (size_t)bh * Kdim * Ddim;
        bf16* dl = g_vp_lo + (size_t)bh * Kdim * Ddim;
#pragma unroll
        for (int l = 0; l < 16; l++) {
            int v4i = t + l * 256;
            int kk = v4i >> 4, d4 = v4i & 15;
            float4 v = *(const float4*)&stage[(size_t)kk * 68 + d4 * 4];
            uint2 h, lo2;
            split4(v, h, lo2);
            *(uint2*)&dh[(size_t)kk * Ddim + d4 * 4] = h;
            *(uint2*)&dl[(size_t)kk * Ddim + d4 * 4] = lo2;
        }
    }
}

// ---------------------------------------------------------------------------
// B1 (persistent): per (slice, bh): KT staged ONCE, then loop 32 q-tiles:
// scores = Q @ KT (3x-bf16) -> softmax -> probs. 256 thr / 8 warps.
// Q for next tile prefetched into registers during GEMM phase.
// ---------------------------------------------------------------------------
#define NB1 4
#define B1_TILES (Sdim / 32 / NB1)           // 32
#define B1_QLDE 72
#define B1_KLDE 264
#define B1_SCLD 260
#define B1_QH 0
#define B1_QL 4608
#define B1_KH 9216
#define B1_KL 43008
#define B1_SC 76800
#define B1_SMEM 110080

__global__ __launch_bounds__(256) void attn_scores(
    const float* __restrict__ q, float* __restrict__ pbuf)
{
    extern __shared__ char smraw[];
    const uint32_t sb = smem_u32(smraw);
    const int bh = blockIdx.y;
    const int tile0 = blockIdx.x * B1_TILES;
    const int t = threadIdx.x, wid = t >> 5;

    // ---- stage KT once (cp.async) ----
    {
        const char* kh = (const char*)(g_kpT_hi + (size_t)bh * Ddim * Kdim);
        const char* kl = (const char*)(g_kpT_lo + (size_t)bh * Ddim * Kdim);
#pragma unroll
        for (int l = 0; l < 8; l++) {        // 2048 chunks per array (64 x 512B)
            int c = t + l * 256;
            int row = c >> 5, off = c & 31;
            cpa16(sb + B1_KH + row * 528 + off * 16, kh + row * 512 + off * 16);
            cpa16(sb + B1_KL + row * 528 + off * 16, kl + row * 512 + off * 16);
        }
        CPA_COMMIT();
    }

    const float* qbh = q + (size_t)bh * Sdim * Ddim;
    float4 qr[2];

    auto ldgQ = [&](int tile) {              // 512 float4 = 32 rows x 16
#pragma unroll
        for (int l = 0; l < 2; l++) {
            int idx = t + l * 256;
            int row = idx >> 4, c4 = idx & 15;
            qr[l] = *(const float4*)&qbh[(size_t)(tile * 32 + row) * Ddim + c4 * 4];
        }
    };
    auto stsQ = [&]() {
        bf16* QH = (bf16*)(smraw + B1_QH);
        bf16* QL = (bf16*)(smraw + B1_QL);
#pragma unroll
        for (int l = 0; l < 2; l++) {
            int idx = t + l * 256;
            int row = idx >> 4, c4 = idx & 15;
            uint2 h, lo;
            split4(qr[l], h, lo);
            *(uint2*)&QH[row * B1_QLDE + c4 * 4] = h;
            *(uint2*)&QL[row * B1_QLDE + c4 * 4] = lo;
        }
    };

    // stage Q(tile0)
    ldgQ(tile0);
    stsQ();
    CPA_WAIT0();
    __syncthreads();

    float* Sc = (float*)(smraw + B1_SC);
    const bf16* QH = (const bf16*)(smraw + B1_QH);
    const bf16* QL = (const bf16*)(smraw + B1_QL);
    const bf16* KH = (const bf16*)(smraw + B1_KH);
    const bf16* KL = (const bf16*)(smraw + B1_KL);

    for (int i = 0; i < B1_TILES; i++) {
        const int tile = tile0 + i;
        const int q0 = tile * 32;

        if (i + 1 < B1_TILES) ldgQ(tile + 1);   // prefetch (latency under GEMM)

        // ---- P1: warp tile M=32 x N=32 at n0 = wid*32 ----
        {
            const int n0 = wid * 32;
            wmma::fragment<wmma::accumulator, 16, 16, 16, float> acc[2][2];
#pragma unroll
            for (int mi = 0; mi < 2; mi++)
#pragma unroll
                for (int ni = 0; ni < 2; ni++) wmma::fill_fragment(acc[mi][ni], 0.0f);
#pragma unroll
            for (int ks = 0; ks < 4; ks++) {
                const int d0 = ks * 16;
                wmma::fragment<wmma::matrix_b, 16, 16, 16, bf16, wmma::row_major> bh2[2], bl2[2];
#pragma unroll
                for (int ni = 0; ni < 2; ni++) {
                    wmma::load_matrix_sync(bh2[ni], KH + d0 * B1_KLDE + n0 + ni * 16, B1_KLDE);
                    wmma::load_matrix_sync(bl2[ni], KL + d0 * B1_KLDE + n0 + ni * 16, B1_KLDE);
                }
#pragma unroll
                for (int mi = 0; mi < 2; mi++) {
                    wmma::fragment<wmma::matrix_a, 16, 16, 16, bf16, wmma::row_major> ah2, al2;
                    wmma::load_matrix_sync(ah2, QH + (mi * 16) * B1_QLDE + d0, B1_QLDE);
                    wmma::load_matrix_sync(al2, QL + (mi * 16) * B1_QLDE + d0, B1_QLDE);
#pragma unroll
                    for (int ni = 0; ni < 2; ni++) {
                        wmma::mma_sync(acc[mi][ni], ah2, bl2[ni], acc[mi][ni]);
                        wmma::mma_sync(acc[mi][ni], al2, bh2[ni], acc[mi][ni]);
                        wmma::mma_sync(acc[mi][ni], ah2, bh2[ni], acc[mi][ni]);
                    }
                }
            }
#pragma unroll
            for (int mi = 0; mi < 2; mi++)
#pragma unroll
                for (int ni = 0; ni < 2; ni++) {
#pragma unroll
                    for (int e = 0; e < acc[mi][ni].num_elements; e++)
                        acc[mi][ni].x[e] *= 0.125f;
                    wmma::store_matrix_sync(Sc + (mi * 16) * B1_SCLD + n0 + ni * 16,
                                            acc[mi][ni], B1_SCLD, wmma::mem_row_major);
                }
        }
        __syncthreads();                     // Sc ready; Q free

        if (i + 1 < B1_TILES) stsQ();        // stage next Q (overlaps softmax)

        // ---- softmax: 32 rows x 8 lanes x 32 cols ----
        {
            const int row = t >> 3;
            const int seg = t & 7;
            float v[32];
            float* base = Sc + row * B1_SCLD + seg * 32;
#pragma unroll
            for (int j = 0; j < 8; j++) {
                float4 f = *(const float4*)&base[j * 4];
                v[j * 4] = f.x; v[j * 4 + 1] = f.y; v[j * 4 + 2] = f.z; v[j * 4 + 3] = f.w;
            }
            float mx = -1e30f;
#pragma unroll
            for (int k2 = 0; k2 < 32; k2++) mx = fmaxf(mx, v[k2]);
#pragma unroll
            for (int o = 1; o < 8; o <<= 1)
                mx = fmaxf(mx, __shfl_xor_sync(0xffffffffu, mx, o));
            float sum = 0.0f;
#pragma unroll
            for (int k2 = 0; k2 < 32; k2++) { v[k2] = __expf(v[k2] - mx); sum += v[k2]; }
#pragma unroll
            for (int o = 1; o < 8; o <<= 1)
                sum += __shfl_xor_sync(0xffffffffu, sum, o);
            float inv = __fdividef(1.0f, sum);
#pragma unroll
            for (int j = 0; j < 8; j++)
                *(float4*)&base[j * 4] =
                    make_float4(v[j * 4] * inv, v[j * 4 + 1] * inv,
                                v[j * 4 + 2] * inv, v[j * 4 + 3] * inv);
        }
        __syncthreads();                     // softmax visible

        // ---- probs -> gmem (coalesced) ----
        {
            float* pb = pbuf + ((size_t)bh * Sdim + q0) * Kdim;
#pragma unroll
            for (int l = 0; l < 8; l++) {
                int v4i = t + l * 256;       // 2048 float4 = 32 x 256
                int row = v4i >> 6, c4 = v4i & 63;
                *(float4*)&pb[(size_t)row * Kdim + c4 * 4] =
                    *(const float4*)&Sc[row * B1_SCLD + c4 * 4];
            }
        }
        __syncthreads();                     // protect Sc before next P1 stores
    }
}

// ---------------------------------------------------------------------------
// B2 (persistent): per (slice, bh): V staged ONCE, then loop 32 q-tiles:
// out = P @ Vproj (3x-bf16). P prefetched to regs, split in STS path.
// 256 thr / 8 warps (2m x 4n of 16x16).
// ---------------------------------------------------------------------------
#define B2_TILES (Sdim / 32 / NB1)           // 32
#define B2_PLDE 264
#define B2_VLDE 72
#define B2_PH 0
#define B2_PL 16896
#define B2_VH 33792
#define B2_VL 70656
#define B2_SMEM 107520

__global__ __launch_bounds__(256) void attn_out(
    const float* __restrict__ pbuf, float* __restrict__ out)
{
    extern __shared__ char smraw[];
    const uint32_t sb = smem_u32(smraw);
    const int bh = blockIdx.y;
    const int tile0 = blockIdx.x * B2_TILES;
    const int t = threadIdx.x, wid = t >> 5;

    // ---- stage V once (cp.async) ----
    {
        const char* vh = (const char*)(g_vp_hi + (size_t)bh * Kdim * Ddim);
        const char* vl = (const char*)(g_vp_lo + (size_t)bh * Kdim * Ddim);
#pragma unroll
        for (int l = 0; l < 8; l++) {        // 2048 chunks per array (256 x 128B)
            int c = t + l * 256;
            int row = c >> 3, off = c & 7;
            cpa16(sb + B2_VH + row * 144 + off * 16, vh + row * 128 + off * 16);
            cpa16(sb + B2_VL + row * 144 + off * 16, vl + row * 128 + off * 16);
        }
        CPA_COMMIT();
    }

    const float* pgbh = pbuf + (size_t)bh * Sdim * Kdim;
    float4 pr[8];

    auto ldgP = [&](int tile) {              // 2048 float4 = 32 rows x 64
#pragma unroll
        for (int l = 0; l < 8; l++) {
            int idx = t + l * 256;
            int row = idx >> 6, c4 = idx & 63;
            pr[l] = *(const float4*)&pgbh[(size_t)(tile * 32 + row) * Kdim + c4 * 4];
        }
    };
    auto stsP = [&]() {
        bf16* PH = (bf16*)(smraw + B2_PH);
        bf16* PL = (bf16*)(smraw + B2_PL);
#pragma unroll
        for (int l = 0; l < 8; l++) {
            int idx = t + l * 256;
            int row = idx >> 6, c4 = idx & 63;
            uint2 h, lo;
            split4(pr[l], h, lo);
            *(uint2*)&PH[row * B2_PLDE + c4 * 4] = h;
            *(uint2*)&PL[row * B2_PLDE + c4 * 4] = lo;
        }
    };

    ldgP(tile0);
    stsP();
    CPA_WAIT0();
    __syncthreads();

    const bf16* PH = (const bf16*)(smraw + B2_PH);
    const bf16* PL = (const bf16*)(smraw + B2_PL);
    const bf16* VH = (const bf16*)(smraw + B2_VH);
    const bf16* VL = (const bf16*)(smraw + B2_VL);

    for (int i = 0; i < B2_TILES; i++) {
        const int tile = tile0 + i;
        const int q0 = tile * 32;

        if (i + 1 < B2_TILES) ldgP(tile + 1);   // prefetch under GEMM

        // ---- out GEMM: warp m0=(wid&1)*16, n0=(wid>>1)*16 ----
        {
            const int m0 = (wid & 1) * 16;
            const int n0 = (wid >> 1) * 16;
            wmma::fragment<wmma::accumulator, 16, 16, 16, float> oacc;
            wmma::fill_fragment(oacc, 0.0f);
#pragma unroll 8
            for (int ks = 0; ks < 16; ks++) {
                const int k0 = ks * 16;
                wmma::fragment<wmma::matrix_a, 16, 16, 16, bf16, wmma::row_major> ah2, al2;
                wmma::fragment<wmma::matrix_b, 16, 16, 16, bf16, wmma::row_major> bh2, bl2;
                wmma::load_matrix_sync(ah2, PH + (size_t)m0 * B2_PLDE + k0, B2_PLDE);
                wmma::load_matrix_sync(al2, PL + (size_t)m0 * B2_PLDE + k0, B2_PLDE);
                wmma::load_matrix_sync(bh2, VH + (size_t)k0 * B2_VLDE + n0, B2_VLDE);
                wmma::load_matrix_sync(bl2, VL + (size_t)k0 * B2_VLDE + n0, B2_VLDE);
                wmma::mma_sync(oacc, ah2, bl2, oacc);
                wmma::mma_sync(oacc, al2, bh2, oacc);
                wmma::mma_sync(oacc, ah2, bh2, oacc);
            }
            float* ob = out + ((size_t)bh * Sdim + q0 + m0) * Ddim + n0;
            wmma::store_matrix_sync(ob, oacc, Ddim, wmma::mem_row_major);
        }
        __syncthreads();                     // all P/V frag loads done

        if (i + 1 < B2_TILES) stsP();        // stage next P
        __syncthreads();
    }
}

// ---------------------------------------------------------------------------
extern "C" void kernel_launch(void* const* d_in, const int* in_sizes, int n_in,
                              void* d_out, int out_size)
{
    const float* q    = (const float*)d_in[0];
    const float* k    = (const float*)d_in[1];
    const float* v    = (const float*)d_in[2];
    const float* mask = (const float*)d_in[3];
    const float* pk   = (const float*)d_in[4];
    const float* pv   = (const float*)d_in[5];

    float* out = (float*)d_out;
    const long OUT_ELEMS = (long)BH * Sdim * Ddim;   // 33,554,432
    float* probs = ((long)out_size > OUT_ELEMS) ? (out + OUT_ELEMS) : nullptr;

    float* pbuf = probs;
    if (!pbuf) cudaGetSymbolAddress((void**)&pbuf, g_probs_fb);

    cudaFuncSetAttribute(proj_gemm, cudaFuncAttributeMaxDynamicSharedMemorySize,
                         PROJ_SMEM);
    cudaFuncSetAttribute(attn_scores, cudaFuncAttributeMaxDynamicSharedMemorySize,
                         B1_SMEM);
    cudaFuncSetAttribute(attn_out, cudaFuncAttributeMaxDynamicSharedMemorySize,
                         B2_SMEM);

    bf16 *pAhi, *pAlo;
    cudaGetSymbolAddress((void**)&pAhi, g_pA_hi);
    cudaGetSymbolAddress((void**)&pAlo, g_pA_lo);
    const size_t pn4 = (size_t)Sdim * Kdim / 4;

    split_plain<<<512, 256>>>(pk, pAhi, pAlo, pn4);
    split_plain<<<512, 256>>>(pv, pAhi + (size_t)Sdim * Kdim,
                              pAlo + (size_t)Sdim * Kdim, pn4);

    proj_gemm<<<dim3(BH, 2), 256, PROJ_SMEM>>>(k, v, mask);
    attn_scores<<<dim3(NB1, BH), 256, B1_SMEM>>>(q, pbuf);
    attn_out<<<dim3(NB1, BH), 256, B2_SMEM>>>(pbuf, out);
}

// round 17
// speedup vs baseline: 1.2465x; 1.2465x over previous
#include <cuda_runtime.h>
#include <mma.h>
#include <cuda_bf16.h>
#include <cuda_fp16.h>
#include <cstdint>

using namespace nvcuda;

#define Bdim 8
#define Hdim 16
#define Sdim 4096
#define Ddim 64
#define Kdim 256
#define BH (Bdim * Hdim)

typedef __nv_bfloat16 bf16;

// ---------------------------------------------------------------------------
// Scratch (no allocation; __device__ globals)
// ---------------------------------------------------------------------------
__device__ bf16 g_pA_hi[(size_t)2 * Sdim * Kdim];      // [which][n][kk]
__device__ bf16 g_pA_lo[(size_t)2 * Sdim * Kdim];
__device__ bf16 g_kpT_hi[(size_t)BH * Ddim * Kdim];    // [bh][d][kk]
__device__ bf16 g_kpT_lo[(size_t)BH * Ddim * Kdim];
__device__ __half g_vp_f16[(size_t)BH * Kdim * Ddim];  // [bh][kk][d]  (fp16)
__device__ float g_probs_fb[(size_t)BH * Sdim * Kdim]; // fallback if probs==null

// ---------------------------------------------------------------------------
// helpers
// ---------------------------------------------------------------------------
__device__ __forceinline__ uint32_t smem_u32(const void* p) {
    uint32_t a;
    asm("{ .reg .u64 t; cvta.to.shared.u64 t, %1; cvt.u32.u64 %0, t; }"
        : "=r"(a) : "l"(p));
    return a;
}
__device__ __forceinline__ void cpa16(uint32_t dst, const void* src) {
    asm volatile("cp.async.cg.shared.global [%0], [%1], 16;" :: "r"(dst), "l"(src));
}
#define CPA_COMMIT() asm volatile("cp.async.commit_group;" ::: "memory")
#define CPA_WAIT0()  asm volatile("cp.async.wait_group 0;" ::: "memory")

// split float -> bf16 hi + bf16 lo (lo = rn(x - hi))
__device__ __forceinline__ void splitbf(float x, bf16& h, bf16& l) {
    h = __float2bfloat16(x);
    l = __float2bfloat16(x - __bfloat162float(h));
}
__device__ __forceinline__ void split4(float4 v, uint2& ho, uint2& lo) {
    bf16 h0, h1, h2, h3, l0, l1, l2, l3;
    splitbf(v.x, h0, l0); splitbf(v.y, h1, l1);
    splitbf(v.z, h2, l2); splitbf(v.w, h3, l3);
    __nv_bfloat162 hp0(h0, h1), hp1(h2, h3), lp0(l0, l1), lp1(l2, l3);
    ho.x = *(uint32_t*)&hp0; ho.y = *(uint32_t*)&hp1;
    lo.x = *(uint32_t*)&lp0; lo.y = *(uint32_t*)&lp1;
}
// float4 -> packed 4 x fp16 (uint2)
__device__ __forceinline__ uint2 tohalf4(float4 v) {
    __half2 h0 = __floats2half2_rn(v.x, v.y);
    __half2 h1 = __floats2half2_rn(v.z, v.w);
    uint2 u;
    u.x = *(uint32_t*)&h0;
    u.y = *(uint32_t*)&h1;
    return u;
}

// ---------------------------------------------------------------------------
// Pre-pass: split proj_k / proj_v (tiny: 2 x 4 MB)
// ---------------------------------------------------------------------------
__global__ __launch_bounds__(256) void split_plain(
    const float* __restrict__ src, bf16* __restrict__ hi, bf16* __restrict__ lo,
    size_t n4)
{
    for (size_t i = (size_t)blockIdx.x * 256 + threadIdx.x; i < n4;
         i += (size_t)gridDim.x * 256) {
        uint2 h, l;
        split4(((const float4*)src)[i], h, l);
        ((uint2*)hi)[i] = h;
        ((uint2*)lo)[i] = l;
    }
}

// ---------------------------------------------------------------------------
// Stage A: per (bh, which): C[kk=256, d=64] = sum_n proj[n,kk] * (kv[n,d]*m[n])
// 3x-bf16 WMMA. A pre-split via cp.async double-buffer; B via fused
// LDG -> mask+split -> STS double-buffer. 256 thr / 8 warps; 64x32 warp tile.
// Epilogue: k-proj -> transposed bf16 hi/lo; v-proj -> fp16 single.
// ---------------------------------------------------------------------------
#define PA_LDE 264
#define PB_LDE 72
#define SA_B (32 * PA_LDE * 2)
#define SB_B (32 * PB_LDE * 2)
#define OFF_AH 0
#define OFF_AL (2 * SA_B)
#define OFF_BH (4 * SA_B)
#define OFF_BL (4 * SA_B + 2 * SB_B)
#define PROJ_SMEM (4 * SA_B + 4 * SB_B)    // 86016
#define NCH (Sdim / 32)

__global__ __launch_bounds__(256) void proj_gemm(
    const float* __restrict__ kin, const float* __restrict__ vin,
    const float* __restrict__ mask)
{
    extern __shared__ char smraw[];
    const uint32_t sb = smem_u32(smraw);
    const int bh = blockIdx.x, which = blockIdx.y, b = bh >> 4;
    const int t = threadIdx.x, wid = t >> 5;
    const int m0 = (wid & 3) * 64;
    const int n0c = (wid >> 2) * 32;

    const char* Ah = (const char*)(g_pA_hi + (size_t)which * Sdim * Kdim);
    const char* Al = (const char*)(g_pA_lo + (size_t)which * Sdim * Kdim);
    const float* Bg = (which ? vin : kin) + (size_t)bh * Sdim * Ddim;
    const float* mk = mask + (size_t)b * Sdim;

    wmma::fragment<wmma::accumulator, 16, 16, 16, float> acc[4][2];
#pragma unroll
    for (int mi = 0; mi < 4; mi++)
#pragma unroll
        for (int ni = 0; ni < 2; ni++) wmma::fill_fragment(acc[mi][ni], 0.0f);

    float4 br[2];
    float brm[2];

    auto issueA = [&](int ch, int buf) {
        const size_t aoff = (size_t)ch * 32 * 512;
#pragma unroll
        for (int l = 0; l < 4; l++) {
            int c = t + l * 256;
            int row = c >> 5, off = c & 31;
            cpa16(sb + OFF_AH + buf * SA_B + row * 528 + off * 16,
                  Ah + aoff + row * 512 + off * 16);
            cpa16(sb + OFF_AL + buf * SA_B + row * 528 + off * 16,
                  Al + aoff + row * 512 + off * 16);
        }
    };
    auto ldgB = [&](int ch) {
#pragma unroll
        for (int l = 0; l < 2; l++) {
            int idx = t + l * 256;
            int row = idx >> 4, c4 = idx & 15;
            br[l]  = *(const float4*)&Bg[(size_t)(ch * 32 + row) * Ddim + c4 * 4];
            brm[l] = mk[ch * 32 + row];
        }
    };
    auto stsB = [&](int buf) {
        bf16* BHp = (bf16*)(smraw + OFF_BH + buf * SB_B);
        bf16* BLp = (bf16*)(smraw + OFF_BL + buf * SB_B);
#pragma unroll
        for (int l = 0; l < 2; l++) {
            int idx = t + l * 256;
            int row = idx >> 4, c4 = idx & 15;
            float4 v = br[l]; float m = brm[l];
            v.x *= m; v.y *= m; v.z *= m; v.w *= m;
            uint2 h, lo;
            split4(v, h, lo);
            *(uint2*)&BHp[row * PB_LDE + c4 * 4] = h;
            *(uint2*)&BLp[row * PB_LDE + c4 * 4] = lo;
        }
    };
    auto do_mma = [&](int buf) {
        const bf16* AH = (const bf16*)(smraw + OFF_AH + buf * SA_B);
        const bf16* AL = (const bf16*)(smraw + OFF_AL + buf * SA_B);
        const bf16* BHp = (const bf16*)(smraw + OFF_BH + buf * SB_B);
        const bf16* BLp = (const bf16*)(smraw + OFF_BL + buf * SB_B);
#pragma unroll
        for (int ks = 0; ks < 2; ks++) {
            wmma::fragment<wmma::matrix_b, 16, 16, 16, bf16, wmma::row_major> bh2[2], bl2[2];
#pragma unroll
            for (int ni = 0; ni < 2; ni++) {
                wmma::load_matrix_sync(bh2[ni], BHp + (ks * 16) * PB_LDE + n0c + ni * 16, PB_LDE);
                wmma::load_matrix_sync(bl2[ni], BLp + (ks * 16) * PB_LDE + n0c + ni * 16, PB_LDE);
            }
#pragma unroll
            for (int mi = 0; mi < 4; mi++) {
                wmma::fragment<wmma::matrix_a, 16, 16, 16, bf16, wmma::col_major> ah2, al2;
                wmma::load_matrix_sync(ah2, AH + (ks * 16) * PA_LDE + m0 + mi * 16, PA_LDE);
                wmma::load_matrix_sync(al2, AL + (ks * 16) * PA_LDE + m0 + mi * 16, PA_LDE);
#pragma unroll
                for (int ni = 0; ni < 2; ni++) {
                    wmma::mma_sync(acc[mi][ni], ah2, bl2[ni], acc[mi][ni]);
                    wmma::mma_sync(acc[mi][ni], al2, bh2[ni], acc[mi][ni]);
                    wmma::mma_sync(acc[mi][ni], ah2, bh2[ni], acc[mi][ni]);
                }
            }
        }
    };

    ldgB(0);
    issueA(0, 0); CPA_COMMIT();
    CPA_WAIT0();
    stsB(0);
    ldgB(1);
    __syncthreads();

    for (int i = 0; i < NCH; i++) {
        const int cur = i & 1, nxt = cur ^ 1;
        if (i + 1 < NCH) {
            issueA(i + 1, nxt);
            CPA_COMMIT();
            stsB(nxt);
        }
        if (i + 2 < NCH) ldgB(i + 2);
        do_mma(cur);
        if (i + 1 < NCH) CPA_WAIT0();
        __syncthreads();
    }

    float* stage = (float*)smraw;
#pragma unroll
    for (int mi = 0; mi < 4; mi++)
#pragma unroll
        for (int ni = 0; ni < 2; ni++)
            wmma::store_matrix_sync(stage + (size_t)(m0 + mi * 16) * 68 + n0c + ni * 16,
                                    acc[mi][ni], 68, wmma::mem_row_major);
    __syncthreads();

    if (which == 0) {
        bf16* dh = g_kpT_hi + (size_t)bh * Ddim * Kdim;
        bf16* dl = g_kpT_lo + (size_t)bh * Ddim * Kdim;
#pragma unroll
        for (int l = 0; l < 16; l++) {
            int v4i = t + l * 256;
            int d = v4i >> 6, kq = v4i & 63;
            float4 v;
            v.x = stage[(size_t)(kq * 4 + 0) * 68 + d];
            v.y = stage[(size_t)(kq * 4 + 1) * 68 + d];
            v.z = stage[(size_t)(kq * 4 + 2) * 68 + d];
            v.w = stage[(size_t)(kq * 4 + 3) * 68 + d];
            uint2 h, lo2;
            split4(v, h, lo2);
            *(uint2*)&dh[(size_t)d * Kdim + kq * 4] = h;
            *(uint2*)&dl[(size_t)d * Kdim + kq * 4] = lo2;
        }
    } else {
        __half* dst = g_vp_f16 + (size_t)bh * Kdim * Ddim;   // [kk][d] fp16
#pragma unroll
        for (int l = 0; l < 16; l++) {
            int v4i = t + l * 256;
            int kk = v4i >> 4, d4 = v4i & 15;
            float4 v = *(const float4*)&stage[(size_t)kk * 68 + d4 * 4];
            *(uint2*)&dst[(size_t)kk * Ddim + d4 * 4] = tohalf4(v);
        }
    }
}

// ---------------------------------------------------------------------------
// B1: per (bh, 32-q tile): scores = Q @ KT (3x-bf16) -> softmax -> probs.
// 256 thr / 8 warps; warp tile 32(M) x 32(N). smem 110.1 KB -> 2 blocks/SM.
// (R15 structure — persistence reverted.)
// ---------------------------------------------------------------------------
#define B1_QLDE 72
#define B1_KLDE 264
#define B1_SCLD 260
#define B1_QH 0
#define B1_QL 4608
#define B1_KH 9216
#define B1_KL 43008
#define B1_SC 76800
#define B1_SMEM 110080

__global__ __launch_bounds__(256) void attn_scores(
    const float* __restrict__ q, float* __restrict__ pbuf)
{
    extern __shared__ char smraw[];
    const uint32_t sb = smem_u32(smraw);
    const int bh = blockIdx.y;
    const int q0 = blockIdx.x * 32;
    const int t = threadIdx.x, wid = t >> 5;

    // ---- stage KT (cp.async) ----
    {
        const char* kh = (const char*)(g_kpT_hi + (size_t)bh * Ddim * Kdim);
        const char* kl = (const char*)(g_kpT_lo + (size_t)bh * Ddim * Kdim);
#pragma unroll
        for (int l = 0; l < 8; l++) {        // 2048 chunks per array (64 x 512B)
            int c = t + l * 256;
            int row = c >> 5, off = c & 31;
            cpa16(sb + B1_KH + row * 528 + off * 16, kh + row * 512 + off * 16);
            cpa16(sb + B1_KL + row * 528 + off * 16, kl + row * 512 + off * 16);
        }
        CPA_COMMIT();
    }
    // ---- stage Q (LDG -> split -> STS), overlaps cp.async ----
    {
        const float* qg = q + ((size_t)bh * Sdim + q0) * Ddim;
        bf16* QH = (bf16*)(smraw + B1_QH);
        bf16* QL = (bf16*)(smraw + B1_QL);
#pragma unroll
        for (int l = 0; l < 2; l++) {        // 512 float4 = 32 rows x 16
            int idx = t + l * 256;
            int row = idx >> 4, c4 = idx & 15;
            float4 v = *(const float4*)&qg[(size_t)row * Ddim + c4 * 4];
            uint2 h, lo;
            split4(v, h, lo);
            *(uint2*)&QH[row * B1_QLDE + c4 * 4] = h;
            *(uint2*)&QL[row * B1_QLDE + c4 * 4] = lo;
        }
    }
    CPA_WAIT0();
    __syncthreads();

    float* Sc = (float*)(smraw + B1_SC);

    // ---- P1: warp tile M=32 x N=32 at n0 = wid*32 ----
    {
        const int n0 = wid * 32;
        const bf16* QH = (const bf16*)(smraw + B1_QH);
        const bf16* QL = (const bf16*)(smraw + B1_QL);
        const bf16* KH = (const bf16*)(smraw + B1_KH);
        const bf16* KL = (const bf16*)(smraw + B1_KL);
        wmma::fragment<wmma::accumulator, 16, 16, 16, float> acc[2][2];
#pragma unroll
        for (int mi = 0; mi < 2; mi++)
#pragma unroll
            for (int ni = 0; ni < 2; ni++) wmma::fill_fragment(acc[mi][ni], 0.0f);
#pragma unroll
        for (int ks = 0; ks < 4; ks++) {
            const int d0 = ks * 16;
            wmma::fragment<wmma::matrix_b, 16, 16, 16, bf16, wmma::row_major> bh2[2], bl2[2];
#pragma unroll
            for (int ni = 0; ni < 2; ni++) {
                wmma::load_matrix_sync(bh2[ni], KH + d0 * B1_KLDE + n0 + ni * 16, B1_KLDE);
                wmma::load_matrix_sync(bl2[ni], KL + d0 * B1_KLDE + n0 + ni * 16, B1_KLDE);
            }
#pragma unroll
            for (int mi = 0; mi < 2; mi++) {
                wmma::fragment<wmma::matrix_a, 16, 16, 16, bf16, wmma::row_major> ah2, al2;
                wmma::load_matrix_sync(ah2, QH + (mi * 16) * B1_QLDE + d0, B1_QLDE);
                wmma::load_matrix_sync(al2, QL + (mi * 16) * B1_QLDE + d0, B1_QLDE);
#pragma unroll
                for (int ni = 0; ni < 2; ni++) {
                    wmma::mma_sync(acc[mi][ni], ah2, bl2[ni], acc[mi][ni]);
                    wmma::mma_sync(acc[mi][ni], al2, bh2[ni], acc[mi][ni]);
                    wmma::mma_sync(acc[mi][ni], ah2, bh2[ni], acc[mi][ni]);
                }
            }
        }
#pragma unroll
        for (int mi = 0; mi < 2; mi++)
#pragma unroll
            for (int ni = 0; ni < 2; ni++) {
#pragma unroll
                for (int e = 0; e < acc[mi][ni].num_elements; e++)
                    acc[mi][ni].x[e] *= 0.125f;
                wmma::store_matrix_sync(Sc + (mi * 16) * B1_SCLD + n0 + ni * 16,
                                        acc[mi][ni], B1_SCLD, wmma::mem_row_major);
            }
    }
    __syncthreads();

    // ---- P2: softmax. 32 rows x 8 lanes x 32 cols ----
    {
        const int row = t >> 3;
        const int seg = t & 7;
        float v[32];
        float* base = Sc + row * B1_SCLD + seg * 32;
#pragma unroll
        for (int j = 0; j < 8; j++) {
            float4 f = *(const float4*)&base[j * 4];
            v[j * 4] = f.x; v[j * 4 + 1] = f.y; v[j * 4 + 2] = f.z; v[j * 4 + 3] = f.w;
        }
        float mx = -1e30f;
#pragma unroll
        for (int i = 0; i < 32; i++) mx = fmaxf(mx, v[i]);
#pragma unroll
        for (int o = 1; o < 8; o <<= 1)
            mx = fmaxf(mx, __shfl_xor_sync(0xffffffffu, mx, o));
        float sum = 0.0f;
#pragma unroll
        for (int i = 0; i < 32; i++) { v[i] = __expf(v[i] - mx); sum += v[i]; }
#pragma unroll
        for (int o = 1; o < 8; o <<= 1)
            sum += __shfl_xor_sync(0xffffffffu, sum, o);
        float inv = __fdividef(1.0f, sum);
#pragma unroll
        for (int j = 0; j < 8; j++)
            *(float4*)&base[j * 4] =
                make_float4(v[j * 4] * inv, v[j * 4 + 1] * inv,
                            v[j * 4 + 2] * inv, v[j * 4 + 3] * inv);
    }
    __syncthreads();

    // ---- P3: probs -> gmem (coalesced) ----
    {
        float* pb = pbuf + ((size_t)bh * Sdim + q0) * Kdim;
#pragma unroll
        for (int l = 0; l < 8; l++) {
            int v4i = t + l * 256;               // 2048 float4 = 32 x 256
            int row = v4i >> 6, c4 = v4i & 63;
            *(float4*)&pb[(size_t)row * Kdim + c4 * 4] =
                *(const float4*)&Sc[row * B1_SCLD + c4 * 4];
        }
    }
}

// ---------------------------------------------------------------------------
// B2: per (bh, 32-q tile): out = P @ Vproj, SINGLE-PRODUCT fp16.
// P re-read from probs gmem, fp16-converted in STS; V fp16 via cp.async.
// 256 thr / 8 warps (2m x 4n of 16x16). smem 52.5 KB -> 4 blocks/SM.
// ---------------------------------------------------------------------------
#define B2_PLDE 264
#define B2_VLDE 72
#define B2_P 0
#define B2_V 16896                          // 32*264*2
#define B2_SMEM (B2_V + 256 * B2_VLDE * 2)  // 53760

__global__ __launch_bounds__(256) void attn_out(
    const float* __restrict__ pbuf, float* __restrict__ out)
{
    extern __shared__ char smraw[];
    const uint32_t sb = smem_u32(smraw);
    const int bh = blockIdx.y;
    const int q0 = blockIdx.x * 32;
    const int t = threadIdx.x, wid = t >> 5;

    // ---- stage V fp16 (cp.async): 2048 chunks (256 rows x 128B) ----
    {
        const char* vg = (const char*)(g_vp_f16 + (size_t)bh * Kdim * Ddim);
#pragma unroll
        for (int l = 0; l < 8; l++) {
            int c = t + l * 256;
            int row = c >> 3, off = c & 7;
            cpa16(sb + B2_V + row * 144 + off * 16, vg + row * 128 + off * 16);
        }
        CPA_COMMIT();
    }
    // ---- stage P (LDG probs fp32 -> fp16 -> STS), overlaps cp.async ----
    {
        const float* pg = pbuf + ((size_t)bh * Sdim + q0) * Kdim;
        __half* PH = (__half*)(smraw + B2_P);
#pragma unroll
        for (int l = 0; l < 8; l++) {        // 2048 float4 = 32 rows x 64
            int idx = t + l * 256;
            int row = idx >> 6, c4 = idx & 63;
            float4 v = *(const float4*)&pg[(size_t)row * Kdim + c4 * 4];
            *(uint2*)&PH[row * B2_PLDE + c4 * 4] = tohalf4(v);
        }
    }
    CPA_WAIT0();
    __syncthreads();

    // ---- out GEMM (fp16 single product): warp m0=(wid&1)*16, n0=(wid>>1)*16
    {
        const int m0 = (wid & 1) * 16;
        const int n0 = (wid >> 1) * 16;
        const __half* PH = (const __half*)(smraw + B2_P);
        const __half* VH = (const __half*)(smraw + B2_V);
        wmma::fragment<wmma::accumulator, 16, 16, 16, float> oacc;
        wmma::fill_fragment(oacc, 0.0f);
#pragma unroll 8
        for (int ks = 0; ks < 16; ks++) {
            const int k0 = ks * 16;
            wmma::fragment<wmma::matrix_a, 16, 16, 16, __half, wmma::row_major> af;
            wmma::fragment<wmma::matrix_b, 16, 16, 16, __half, wmma::row_major> bf;
            wmma::load_matrix_sync(af, PH + (size_t)m0 * B2_PLDE + k0, B2_PLDE);
            wmma::load_matrix_sync(bf, VH + (size_t)k0 * B2_VLDE + n0, B2_VLDE);
            wmma::mma_sync(oacc, af, bf, oacc);
        }
        float* ob = out + ((size_t)bh * Sdim + q0 + m0) * Ddim + n0;
        wmma::store_matrix_sync(ob, oacc, Ddim, wmma::mem_row_major);
    }
}

// ---------------------------------------------------------------------------
extern "C" void kernel_launch(void* const* d_in, const int* in_sizes, int n_in,
                              void* d_out, int out_size)
{
    const float* q    = (const float*)d_in[0];
    const float* k    = (const float*)d_in[1];
    const float* v    = (const float*)d_in[2];
    const float* mask = (const float*)d_in[3];
    const float* pk   = (const float*)d_in[4];
    const float* pv   = (const float*)d_in[5];

    float* out = (float*)d_out;
    const long OUT_ELEMS = (long)BH * Sdim * Ddim;   // 33,554,432
    float* probs = ((long)out_size > OUT_ELEMS) ? (out + OUT_ELEMS) : nullptr;

    float* pbuf = probs;
    if (!pbuf) cudaGetSymbolAddress((void**)&pbuf, g_probs_fb);

    cudaFuncSetAttribute(proj_gemm, cudaFuncAttributeMaxDynamicSharedMemorySize,
                         PROJ_SMEM);
    cudaFuncSetAttribute(attn_scores, cudaFuncAttributeMaxDynamicSharedMemorySize,
                         B1_SMEM);
    cudaFuncSetAttribute(attn_out, cudaFuncAttributeMaxDynamicSharedMemorySize,
                         B2_SMEM);

    bf16 *pAhi, *pAlo;
    cudaGetSymbolAddress((void**)&pAhi, g_pA_hi);
    cudaGetSymbolAddress((void**)&pAlo, g_pA_lo);
    const size_t pn4 = (size_t)Sdim * Kdim / 4;

    split_plain<<<512, 256>>>(pk, pAhi, pAlo, pn4);
    split_plain<<<512, 256>>>(pv, pAhi + (size_t)Sdim * Kdim,
                              pAlo + (size_t)Sdim * Kdim, pn4);

    proj_gemm<<<dim3(BH, 2), 256, PROJ_SMEM>>>(k, v, mask);
    attn_scores<<<dim3(Sdim / 32, BH), 256, B1_SMEM>>>(q, pbuf);
    attn_out<<<dim3(Sdim / 32, BH), 256, B2_SMEM>>>(pbuf, out);
}